// round 2
// baseline (speedup 1.0000x reference)
#include <cuda_runtime.h>

#define BB 16
#define TT 512
#define NVAR 21
#define PS 16
#define STR 8
#define PRED 96
#define DM 128
#define DS 16
#define DIN 256
#define DTR 8
#define SEA 512
#define PN 64
#define BN_TOT (BB*NVAR)      /* 336 */
#define ROWS (BN_TOT*PN)      /* 21504 */
#define KSPLIT 8

// ---------------- scratch (static device globals; no allocation) ----------------
__device__ float g_h0[ROWS*DM];
__device__ float g_S[ROWS*SEA];
__device__ float g_attn[ROWS*DM];
__device__ float g_hb[ROWS*DM];
__device__ float g_xz[ROWS*2*DIN];
__device__ float g_y[ROWS*DIN];
__device__ float g_y2[ROWS*DM];
__device__ float g_parts[KSPLIT*BN_TOT*2*PRED];
__device__ float g_gbuf[BN_TOT*2*PRED];
__device__ float g_mean[BN_TOT];
__device__ float g_std[BN_TOT];

__device__ __forceinline__ float geluf(float x) {
    return 0.5f * x * (1.0f + erff(x * 0.70710678118654752f));
}
__device__ __forceinline__ float siluf(float x) {
    return x / (1.0f + expf(-x));
}

// ---------------- kernel 1: RevIN stats + patches + mlp1 ----------------
// one block per bn=(b,v); 128 threads (thread = output channel d)
__global__ void k_revin_mlp1(const float* __restrict__ x,
                             const float* __restrict__ revin_w,
                             const float* __restrict__ revin_b,
                             const float* __restrict__ mlp1_w,
                             const float* __restrict__ mlp1_b)
{
    int bn = blockIdx.x;
    int b = bn / NVAR, v = bn % NVAR;
    int tid = threadIdx.x;
    __shared__ float xs[TT];
    __shared__ float rs[4], rq[4];

    float sum = 0.f, sq = 0.f;
    for (int t = tid; t < TT; t += 128) {
        float val = x[(b * TT + t) * NVAR + v];
        xs[t] = val;
        sum += val; sq += val * val;
    }
    #pragma unroll
    for (int o = 16; o; o >>= 1) {
        sum += __shfl_xor_sync(0xffffffffu, sum, o);
        sq  += __shfl_xor_sync(0xffffffffu, sq , o);
    }
    if ((tid & 31) == 0) { rs[tid >> 5] = sum; rq[tid >> 5] = sq; }
    __syncthreads();
    float ts = rs[0] + rs[1] + rs[2] + rs[3];
    float tq = rq[0] + rq[1] + rq[2] + rq[3];
    float mean = ts * (1.f / TT);
    float var  = tq * (1.f / TT) - mean * mean;
    float stdv = sqrtf(var + 1e-5f);
    float rstd = 1.f / stdv;
    if (tid == 0) { g_mean[bn] = mean; g_std[bn] = stdv; }

    float rw = revin_w[v], rb = revin_b[v];
    for (int t = tid; t < TT; t += 128)
        xs[t] = (xs[t] - mean) * rstd * rw + rb;
    __syncthreads();

    // mlp1: h[bn,p,d] = sum_s patch[p,s] * w[d,s] + b[d], patch index clamped (right-pad repeat)
    float w[PS];
    #pragma unroll
    for (int s = 0; s < PS; s++) w[s] = mlp1_w[tid * PS + s];
    float bias = mlp1_b[tid];
    for (int p = 0; p < PN; p++) {
        int base = p * STR;
        float acc = bias;
        #pragma unroll
        for (int s = 0; s < PS; s++) {
            int t = base + s; if (t > TT - 1) t = TT - 1;
            acc += xs[t] * w[s];
        }
        g_h0[(bn * PN + p) * DM + tid] = acc;
    }
}

// ---------------- generic NT SGEMM: C[M,N] = A[M,K] @ B[N,K]^T -------------
// 64x64 block tile, k-tile 16, 256 threads, 4x4 micro-tile.
// blockIdx.z = split-K slice: accumulates over [z*klen, (z+1)*klen), writes C + z*M*N.
__global__ void __launch_bounds__(256) k_gemm_nt(
    const float* __restrict__ A, const float* __restrict__ B, float* __restrict__ C,
    int M, int N, int K, int klen)
{
    __shared__ float As[16][68];
    __shared__ float Bs[16][68];
    int m0 = blockIdx.x * 64;
    int n0 = blockIdx.y * 64;
    int kb = blockIdx.z * klen;
    C += (size_t)blockIdx.z * M * N;
    int tid = threadIdx.x;
    int tm = tid >> 4, tn = tid & 15;
    int lr = tid >> 2;
    int lk = (tid & 3) * 4;
    bool aValid = (m0 + lr) < M;
    const float* Ap = A + (size_t)(m0 + lr) * K + lk;
    const float* Bp = B + (size_t)(n0 + lr) * K + lk;

    float acc[4][4];
    #pragma unroll
    for (int i = 0; i < 4; i++)
        #pragma unroll
        for (int j = 0; j < 4; j++) acc[i][j] = 0.f;

    for (int k = kb; k < kb + klen; k += 16) {
        float4 av = aValid ? *(const float4*)(Ap + k) : make_float4(0.f, 0.f, 0.f, 0.f);
        float4 bv = *(const float4*)(Bp + k);
        __syncthreads();
        As[lk + 0][lr] = av.x; As[lk + 1][lr] = av.y; As[lk + 2][lr] = av.z; As[lk + 3][lr] = av.w;
        Bs[lk + 0][lr] = bv.x; Bs[lk + 1][lr] = bv.y; Bs[lk + 2][lr] = bv.z; Bs[lk + 3][lr] = bv.w;
        __syncthreads();
        #pragma unroll
        for (int kk = 0; kk < 16; kk++) {
            float4 a = *(const float4*)&As[kk][tm * 4];
            float4 b = *(const float4*)&Bs[kk][tn * 4];
            acc[0][0] += a.x * b.x; acc[0][1] += a.x * b.y; acc[0][2] += a.x * b.z; acc[0][3] += a.x * b.w;
            acc[1][0] += a.y * b.x; acc[1][1] += a.y * b.y; acc[1][2] += a.y * b.z; acc[1][3] += a.y * b.w;
            acc[2][0] += a.z * b.x; acc[2][1] += a.z * b.y; acc[2][2] += a.z * b.z; acc[2][3] += a.z * b.w;
            acc[3][0] += a.w * b.x; acc[3][1] += a.w * b.y; acc[3][2] += a.w * b.z; acc[3][3] += a.w * b.w;
        }
    }
    #pragma unroll
    for (int i = 0; i < 4; i++) {
        int row = m0 + tm * 4 + i;
        if (row < M) {
            float* cp = C + (size_t)row * N + n0 + tn * 4;
            cp[0] = acc[i][0]; cp[1] = acc[i][1]; cp[2] = acc[i][2]; cp[3] = acc[i][3];
        }
    }
}

// ---------------- softmax over rows of 512 (in place) ----------------
__global__ void k_softmax(float* __restrict__ S)
{
    int row = blockIdx.x; int tid = threadIdx.x;
    float* p = S + (size_t)row * SEA;
    float v0 = p[tid], v1 = p[tid + 128], v2 = p[tid + 256], v3 = p[tid + 384];
    float m = fmaxf(fmaxf(v0, v1), fmaxf(v2, v3));
    __shared__ float rr[4];
    __shared__ float ss[4];
    #pragma unroll
    for (int o = 16; o; o >>= 1) m = fmaxf(m, __shfl_xor_sync(0xffffffffu, m, o));
    if ((tid & 31) == 0) rr[tid >> 5] = m;
    __syncthreads();
    m = fmaxf(fmaxf(rr[0], rr[1]), fmaxf(rr[2], rr[3]));
    v0 = expf(v0 - m); v1 = expf(v1 - m); v2 = expf(v2 - m); v3 = expf(v3 - m);
    float s = v0 + v1 + v2 + v3;
    #pragma unroll
    for (int o = 16; o; o >>= 1) s += __shfl_xor_sync(0xffffffffu, s, o);
    if ((tid & 31) == 0) ss[tid >> 5] = s;
    __syncthreads();
    s = ss[0] + ss[1] + ss[2] + ss[3];
    float inv = 1.f / s;
    p[tid] = v0 * inv; p[tid + 128] = v1 * inv; p[tid + 256] = v2 * inv; p[tid + 384] = v3 * inv;
}

// ---------------- LayerNorm + exact GELU + residual ----------------
__global__ void k_ln_gelu_res(const float* __restrict__ lnw, const float* __restrict__ lnb)
{
    int row = blockIdx.x; int tid = threadIdx.x;
    float a = g_attn[(size_t)row * DM + tid];
    float s = a, q = a * a;
    __shared__ float rs[4], rq[4];
    #pragma unroll
    for (int o = 16; o; o >>= 1) {
        s += __shfl_xor_sync(0xffffffffu, s, o);
        q += __shfl_xor_sync(0xffffffffu, q, o);
    }
    if ((tid & 31) == 0) { rs[tid >> 5] = s; rq[tid >> 5] = q; }
    __syncthreads();
    float ts = rs[0] + rs[1] + rs[2] + rs[3];
    float tq = rq[0] + rq[1] + rq[2] + rq[3];
    float mean = ts * (1.f / DM);
    float var  = tq * (1.f / DM) - mean * mean;
    float ln = (a - mean) * rsqrtf(var + 1e-5f) * lnw[tid] + lnb[tid];
    g_hb[(size_t)row * DM + tid] = geluf(ln) + g_h0[(size_t)row * DM + tid];
}

// ---------------- Mamba mid: conv+silu, x_proj, dt_proj+softplus, scan, gate ---
// one block per sequence bn; 256 threads (thread = inner channel d)
__global__ void __launch_bounds__(256, 1) k_mamba(
    const float* __restrict__ conv_w, const float* __restrict__ conv_b,
    const float* __restrict__ x_proj_w, const float* __restrict__ dt_proj_w,
    const float* __restrict__ dt_proj_b, const float* __restrict__ A_log,
    const float* __restrict__ D_ssm)
{
    extern __shared__ float sm[];
    float* xc_s  = sm;                      // PN*DIN
    float* dl_s  = xc_s + PN * DIN;         // PN*DIN
    float* xpw_s = dl_s + PN * DIN;         // 40*DIN (transposed: [dd*40 + j])
    float* dbl_s = xpw_s + 40 * DIN;        // PN*40

    int bn = blockIdx.x, tid = threadIdx.x, d = tid;

    // load x_proj_w transposed for conflict-free inner product
    for (int i = tid; i < 40 * DIN; i += 256) {
        int j = i / DIN, dd = i % DIN;
        xpw_s[dd * 40 + j] = x_proj_w[i];
    }

    // causal depthwise conv (width 4) + silu
    float cw0 = conv_w[d * 4], cw1 = conv_w[d * 4 + 1], cw2 = conv_w[d * 4 + 2], cw3 = conv_w[d * 4 + 3];
    float cb = conv_b[d];
    float w1 = 0.f, w2 = 0.f, w3 = 0.f;
    const float* xzb = g_xz + (size_t)bn * PN * 2 * DIN;
    for (int t = 0; t < PN; t++) {
        float xv = xzb[t * 2 * DIN + d];
        float c = w1 * cw0 + w2 * cw1 + w3 * cw2 + xv * cw3 + cb;
        w1 = w2; w2 = w3; w3 = xv;
        xc_s[t * DIN + d] = siluf(c);
    }
    __syncthreads();

    // dbl = xc @ x_proj_w^T  (64x40)
    for (int idx = tid; idx < PN * 40; idx += 256) {
        int t = idx / 40, j = idx % 40;
        const float* xr = xc_s + t * DIN;
        float acc = 0.f;
        #pragma unroll 8
        for (int dd = 0; dd < DIN; dd++) acc += xr[dd] * xpw_s[dd * 40 + j];
        dbl_s[idx] = acc;
    }
    __syncthreads();

    // delta = softplus(dt @ dt_proj_w^T + dt_b)
    float dtw[DTR];
    #pragma unroll
    for (int r = 0; r < DTR; r++) dtw[r] = dt_proj_w[d * DTR + r];
    float dtb = dt_proj_b[d];
    for (int t = 0; t < PN; t++) {
        float a = dtb;
        #pragma unroll
        for (int r = 0; r < DTR; r++) a += dbl_s[t * 40 + r] * dtw[r];
        dl_s[t * DIN + d] = (a > 20.f) ? a : log1pf(expf(a));
    }
    __syncthreads();

    // selective scan (16 states per channel) + skip + gate
    float Ar[DS];
    #pragma unroll
    for (int s = 0; s < DS; s++) Ar[s] = -expf(A_log[d * DS + s]);
    float hst[DS];
    #pragma unroll
    for (int s = 0; s < DS; s++) hst[s] = 0.f;
    float Dd = D_ssm[d];
    float* yb = g_y + (size_t)bn * PN * DIN;
    for (int t = 0; t < PN; t++) {
        float dlt = dl_s[t * DIN + d];
        float u = xc_s[t * DIN + d];
        float du = dlt * u;
        float y = 0.f;
        const float* dr = dbl_s + t * 40;
        #pragma unroll
        for (int s = 0; s < DS; s++) {
            float dA = __expf(dlt * Ar[s]);
            hst[s] = dA * hst[s] + du * dr[8 + s];
            y += hst[s] * dr[24 + s];
        }
        y += Dd * u;
        float zv = xzb[t * 2 * DIN + DIN + d];
        y *= siluf(zv);
        yb[t * DIN + d] = y;
    }
}

// ---------------- mlp2 split-K reduce + bias + GELU ----------------
__global__ void k_mlp2_reduce(const float* __restrict__ mlp2_b)
{
    int idx = blockIdx.x * 256 + threadIdx.x;
    if (idx >= BN_TOT * 2 * PRED) return;
    float s = 0.f;
    #pragma unroll
    for (int z = 0; z < KSPLIT; z++) s += g_parts[(size_t)z * BN_TOT * 2 * PRED + idx];
    s += mlp2_b[idx % (2 * PRED)];
    g_gbuf[idx] = geluf(s);
}

// ---------------- mlp3 + de-normalize + transpose store ----------------
__global__ void k_final(const float* __restrict__ mlp3_w, const float* __restrict__ mlp3_b,
                        const float* __restrict__ revin_w, const float* __restrict__ revin_b,
                        float* __restrict__ out)
{
    int bn = blockIdx.x; int tid = threadIdx.x;   // tid = pred index (96 threads)
    __shared__ float gs[2 * PRED];
    for (int i = tid; i < 2 * PRED; i += PRED) gs[i] = g_gbuf[bn * 2 * PRED + i];
    __syncthreads();
    float acc = mlp3_b[tid];
    const float* wr = mlp3_w + tid * 2 * PRED;
    #pragma unroll 8
    for (int j = 0; j < 2 * PRED; j++) acc += gs[j] * wr[j];
    int b = bn / NVAR, v = bn % NVAR;
    float o = (acc - revin_b[v]) / (revin_w[v] + 1e-10f);
    o = o * g_std[bn] + g_mean[bn];
    out[(b * PRED + tid) * NVAR + v] = o;
}

// ---------------- launch ----------------
extern "C" void kernel_launch(void* const* d_in, const int* in_sizes, int n_in,
                              void* d_out, int out_size)
{
    const float* x         = (const float*)d_in[0];
    const float* revin_w   = (const float*)d_in[1];
    const float* revin_b   = (const float*)d_in[2];
    const float* mlp1_w    = (const float*)d_in[3];
    const float* mlp1_b    = (const float*)d_in[4];
    const float* mk_w      = (const float*)d_in[5];
    const float* mv_w      = (const float*)d_in[6];
    const float* ln_w      = (const float*)d_in[7];
    const float* ln_b      = (const float*)d_in[8];
    const float* in_proj_w = (const float*)d_in[9];
    const float* conv_w    = (const float*)d_in[10];
    const float* conv_b    = (const float*)d_in[11];
    const float* x_proj_w  = (const float*)d_in[12];
    const float* dt_proj_w = (const float*)d_in[13];
    const float* dt_proj_b = (const float*)d_in[14];
    const float* A_log     = (const float*)d_in[15];
    const float* D_ssm     = (const float*)d_in[16];
    const float* out_proj_w= (const float*)d_in[17];
    const float* mlp2_w    = (const float*)d_in[18];
    const float* mlp2_b    = (const float*)d_in[19];
    const float* mlp3_w    = (const float*)d_in[20];
    const float* mlp3_b    = (const float*)d_in[21];
    float* out = (float*)d_out;

    float *h0, *S, *attn, *hb, *xz, *y, *y2, *parts;
    cudaGetSymbolAddress((void**)&h0,    g_h0);
    cudaGetSymbolAddress((void**)&S,     g_S);
    cudaGetSymbolAddress((void**)&attn,  g_attn);
    cudaGetSymbolAddress((void**)&hb,    g_hb);
    cudaGetSymbolAddress((void**)&xz,    g_xz);
    cudaGetSymbolAddress((void**)&y,     g_y);
    cudaGetSymbolAddress((void**)&y2,    g_y2);
    cudaGetSymbolAddress((void**)&parts, g_parts);

    const int mamba_smem = (PN * DIN * 2 + 40 * DIN + PN * 40) * 4;   // 182272 B
    cudaFuncSetAttribute(k_mamba, cudaFuncAttributeMaxDynamicSharedMemorySize, mamba_smem);

    // 1. RevIN + patches + mlp1
    k_revin_mlp1<<<BN_TOT, 128>>>(x, revin_w, revin_b, mlp1_w, mlp1_b);
    // 2. scores S = h @ mk_w^T
    k_gemm_nt<<<dim3(ROWS / 64, SEA / 64, 1), 256>>>(h0, mk_w, S, ROWS, SEA, DM, DM);
    // 3. softmax
    k_softmax<<<ROWS, 128>>>(S);
    // 4. attn = P @ mv_w^T
    k_gemm_nt<<<dim3(ROWS / 64, DM / 64, 1), 256>>>(S, mv_w, attn, ROWS, DM, SEA, SEA);
    // 5. LN + GELU + residual -> hb
    k_ln_gelu_res<<<ROWS, 128>>>(ln_w, ln_b);
    // 6. xz = hb @ in_proj_w^T
    k_gemm_nt<<<dim3(ROWS / 64, (2 * DIN) / 64, 1), 256>>>(hb, in_proj_w, xz, ROWS, 2 * DIN, DM, DM);
    // 7. mamba mid (conv/x_proj/dt/scan/gate) -> y
    k_mamba<<<BN_TOT, 256, mamba_smem>>>(conv_w, conv_b, x_proj_w, dt_proj_w, dt_proj_b, A_log, D_ssm);
    // 8. y2 = y @ out_proj_w^T
    k_gemm_nt<<<dim3(ROWS / 64, DM / 64, 1), 256>>>(y, out_proj_w, y2, ROWS, DM, DIN, DIN);
    // 9. mlp2 split-K partials: (336 x 8192) @ (192 x 8192)^T
    k_gemm_nt<<<dim3((BN_TOT + 63) / 64, (2 * PRED) / 64, KSPLIT), 256>>>(
        y2, mlp2_w, parts, BN_TOT, 2 * PRED, PN * DM, (PN * DM) / KSPLIT);
    // 10. reduce + bias + GELU
    k_mlp2_reduce<<<(BN_TOT * 2 * PRED + 255) / 256, 256>>>(mlp2_b);
    // 11. mlp3 + de-norm + transposed store
    k_final<<<BN_TOT, PRED>>>(mlp3_w, mlp3_b, revin_w, revin_b, out);
}

// round 3
// speedup vs baseline: 1.0192x; 1.0192x over previous
#include <cuda_runtime.h>

#define BB 16
#define TT 512
#define NVAR 21
#define PS 16
#define STR 8
#define PRED 96
#define DM 128
#define DS 16
#define DIN 256
#define DTR 8
#define SEA 512
#define PN 64
#define BN_TOT (BB*NVAR)      /* 336 */
#define ROWS (BN_TOT*PN)      /* 21504 */
#define KSPLIT 16

// ---------------- scratch (static device globals; no allocation) ----------------
__device__ float g_h0[ROWS*DM];
__device__ float g_S[ROWS*SEA];
__device__ float g_attn[ROWS*DM];
__device__ float g_hb[ROWS*DM];
__device__ float g_xz[ROWS*2*DIN];
__device__ float g_y[ROWS*DIN];
__device__ float g_y2[ROWS*DM];
__device__ float g_parts[KSPLIT*BN_TOT*2*PRED];
__device__ float g_gbuf[BN_TOT*2*PRED];
__device__ float g_mean[BN_TOT];
__device__ float g_std[BN_TOT];

__device__ __forceinline__ float geluf(float x) {
    return 0.5f * x * (1.0f + erff(x * 0.70710678118654752f));
}
__device__ __forceinline__ float siluf(float x) {
    return x / (1.0f + expf(-x));
}

// ---------------- kernel 1: RevIN stats + patches + mlp1 ----------------
__global__ void k_revin_mlp1(const float* __restrict__ x,
                             const float* __restrict__ revin_w,
                             const float* __restrict__ revin_b,
                             const float* __restrict__ mlp1_w,
                             const float* __restrict__ mlp1_b)
{
    int bn = blockIdx.x;
    int b = bn / NVAR, v = bn % NVAR;
    int tid = threadIdx.x;
    __shared__ float xs[TT];
    __shared__ float rs[4], rq[4];

    float sum = 0.f, sq = 0.f;
    for (int t = tid; t < TT; t += 128) {
        float val = x[(b * TT + t) * NVAR + v];
        xs[t] = val;
        sum += val; sq += val * val;
    }
    #pragma unroll
    for (int o = 16; o; o >>= 1) {
        sum += __shfl_xor_sync(0xffffffffu, sum, o);
        sq  += __shfl_xor_sync(0xffffffffu, sq , o);
    }
    if ((tid & 31) == 0) { rs[tid >> 5] = sum; rq[tid >> 5] = sq; }
    __syncthreads();
    float ts = rs[0] + rs[1] + rs[2] + rs[3];
    float tq = rq[0] + rq[1] + rq[2] + rq[3];
    float mean = ts * (1.f / TT);
    float var  = tq * (1.f / TT) - mean * mean;
    float stdv = sqrtf(var + 1e-5f);
    float rstd = 1.f / stdv;
    if (tid == 0) { g_mean[bn] = mean; g_std[bn] = stdv; }

    float rw = revin_w[v], rb = revin_b[v];
    for (int t = tid; t < TT; t += 128)
        xs[t] = (xs[t] - mean) * rstd * rw + rb;
    __syncthreads();

    float w[PS];
    #pragma unroll
    for (int s = 0; s < PS; s++) w[s] = mlp1_w[tid * PS + s];
    float bias = mlp1_b[tid];
    for (int p = 0; p < PN; p++) {
        int base = p * STR;
        float acc = bias;
        #pragma unroll
        for (int s = 0; s < PS; s++) {
            int t = base + s; if (t > TT - 1) t = TT - 1;
            acc += xs[t] * w[s];
        }
        g_h0[(bn * PN + p) * DM + tid] = acc;
    }
}

// ---------------- fast NT SGEMM: 128x128 tile, 8x8 micro-tile ----------------
// C[M,N] = A[M,K] @ B[N,K]^T. Requires M%128==0, N%128==0, K%16==0.
__global__ void __launch_bounds__(256, 2) k_gemm128(
    const float* __restrict__ A, const float* __restrict__ B, float* __restrict__ C,
    int M, int N, int K)
{
    __shared__ float As[16][128];
    __shared__ float Bs[16][128];
    int m0 = blockIdx.x * 128;
    int n0 = blockIdx.y * 128;
    int tid = threadIdx.x;
    int lr = tid >> 1;              // 0..127 (tile row)
    int lk = (tid & 1) * 8;         // 0 or 8 (k offset)
    const float* Ap = A + (size_t)(m0 + lr) * K + lk;
    const float* Bp = B + (size_t)(n0 + lr) * K + lk;
    int tm = (tid >> 4) * 8;
    int tn = (tid & 15) * 8;

    float acc[8][8];
    #pragma unroll
    for (int i = 0; i < 8; i++)
        #pragma unroll
        for (int j = 0; j < 8; j++) acc[i][j] = 0.f;

    float4 a0 = *(const float4*)(Ap);
    float4 a1 = *(const float4*)(Ap + 4);
    float4 b0 = *(const float4*)(Bp);
    float4 b1 = *(const float4*)(Bp + 4);

    for (int k = 16; k <= K; k += 16) {
        __syncthreads();
        As[lk + 0][lr] = a0.x; As[lk + 1][lr] = a0.y; As[lk + 2][lr] = a0.z; As[lk + 3][lr] = a0.w;
        As[lk + 4][lr] = a1.x; As[lk + 5][lr] = a1.y; As[lk + 6][lr] = a1.z; As[lk + 7][lr] = a1.w;
        Bs[lk + 0][lr] = b0.x; Bs[lk + 1][lr] = b0.y; Bs[lk + 2][lr] = b0.z; Bs[lk + 3][lr] = b0.w;
        Bs[lk + 4][lr] = b1.x; Bs[lk + 5][lr] = b1.y; Bs[lk + 6][lr] = b1.z; Bs[lk + 7][lr] = b1.w;
        __syncthreads();
        if (k < K) {
            a0 = *(const float4*)(Ap + k);
            a1 = *(const float4*)(Ap + k + 4);
            b0 = *(const float4*)(Bp + k);
            b1 = *(const float4*)(Bp + k + 4);
        }
        #pragma unroll
        for (int kk = 0; kk < 16; kk++) {
            float af[8], bf[8];
            *(float4*)&af[0] = *(const float4*)&As[kk][tm];
            *(float4*)&af[4] = *(const float4*)&As[kk][tm + 4];
            *(float4*)&bf[0] = *(const float4*)&Bs[kk][tn];
            *(float4*)&bf[4] = *(const float4*)&Bs[kk][tn + 4];
            #pragma unroll
            for (int i = 0; i < 8; i++)
                #pragma unroll
                for (int j = 0; j < 8; j++)
                    acc[i][j] += af[i] * bf[j];
        }
    }

    #pragma unroll
    for (int i = 0; i < 8; i++) {
        float* cp = C + (size_t)(m0 + tm + i) * N + n0 + tn;
        *(float4*)cp       = *(float4*)&acc[i][0];
        *(float4*)(cp + 4) = *(float4*)&acc[i][4];
    }
}

// ---------------- generic NT SGEMM (64x64) for small/odd shapes ----------------
__global__ void __launch_bounds__(256) k_gemm_nt(
    const float* __restrict__ A, const float* __restrict__ B, float* __restrict__ C,
    int M, int N, int K, int klen)
{
    __shared__ float As[16][68];
    __shared__ float Bs[16][68];
    int m0 = blockIdx.x * 64;
    int n0 = blockIdx.y * 64;
    int kb = blockIdx.z * klen;
    C += (size_t)blockIdx.z * M * N;
    int tid = threadIdx.x;
    int tm = tid >> 4, tn = tid & 15;
    int lr = tid >> 2;
    int lk = (tid & 3) * 4;
    bool aValid = (m0 + lr) < M;
    const float* Ap = A + (size_t)(m0 + lr) * K + lk;
    const float* Bp = B + (size_t)(n0 + lr) * K + lk;

    float acc[4][4];
    #pragma unroll
    for (int i = 0; i < 4; i++)
        #pragma unroll
        for (int j = 0; j < 4; j++) acc[i][j] = 0.f;

    for (int k = kb; k < kb + klen; k += 16) {
        float4 av = aValid ? *(const float4*)(Ap + k) : make_float4(0.f, 0.f, 0.f, 0.f);
        float4 bv = *(const float4*)(Bp + k);
        __syncthreads();
        As[lk + 0][lr] = av.x; As[lk + 1][lr] = av.y; As[lk + 2][lr] = av.z; As[lk + 3][lr] = av.w;
        Bs[lk + 0][lr] = bv.x; Bs[lk + 1][lr] = bv.y; Bs[lk + 2][lr] = bv.z; Bs[lk + 3][lr] = bv.w;
        __syncthreads();
        #pragma unroll
        for (int kk = 0; kk < 16; kk++) {
            float4 a = *(const float4*)&As[kk][tm * 4];
            float4 b = *(const float4*)&Bs[kk][tn * 4];
            acc[0][0] += a.x * b.x; acc[0][1] += a.x * b.y; acc[0][2] += a.x * b.z; acc[0][3] += a.x * b.w;
            acc[1][0] += a.y * b.x; acc[1][1] += a.y * b.y; acc[1][2] += a.y * b.z; acc[1][3] += a.y * b.w;
            acc[2][0] += a.z * b.x; acc[2][1] += a.z * b.y; acc[2][2] += a.z * b.z; acc[2][3] += a.z * b.w;
            acc[3][0] += a.w * b.x; acc[3][1] += a.w * b.y; acc[3][2] += a.w * b.z; acc[3][3] += a.w * b.w;
        }
    }
    #pragma unroll
    for (int i = 0; i < 4; i++) {
        int row = m0 + tm * 4 + i;
        if (row < M) {
            float* cp = C + (size_t)row * N + n0 + tn * 4;
            cp[0] = acc[i][0]; cp[1] = acc[i][1]; cp[2] = acc[i][2]; cp[3] = acc[i][3];
        }
    }
}

// ---------------- softmax over rows of 512 (in place) ----------------
__global__ void k_softmax(float* __restrict__ S)
{
    int row = blockIdx.x; int tid = threadIdx.x;
    float* p = S + (size_t)row * SEA;
    float v0 = p[tid], v1 = p[tid + 128], v2 = p[tid + 256], v3 = p[tid + 384];
    float m = fmaxf(fmaxf(v0, v1), fmaxf(v2, v3));
    __shared__ float rr[4];
    __shared__ float ss[4];
    #pragma unroll
    for (int o = 16; o; o >>= 1) m = fmaxf(m, __shfl_xor_sync(0xffffffffu, m, o));
    if ((tid & 31) == 0) rr[tid >> 5] = m;
    __syncthreads();
    m = fmaxf(fmaxf(rr[0], rr[1]), fmaxf(rr[2], rr[3]));
    v0 = expf(v0 - m); v1 = expf(v1 - m); v2 = expf(v2 - m); v3 = expf(v3 - m);
    float s = v0 + v1 + v2 + v3;
    #pragma unroll
    for (int o = 16; o; o >>= 1) s += __shfl_xor_sync(0xffffffffu, s, o);
    if ((tid & 31) == 0) ss[tid >> 5] = s;
    __syncthreads();
    s = ss[0] + ss[1] + ss[2] + ss[3];
    float inv = 1.f / s;
    p[tid] = v0 * inv; p[tid + 128] = v1 * inv; p[tid + 256] = v2 * inv; p[tid + 384] = v3 * inv;
}

// ---------------- LayerNorm + exact GELU + residual ----------------
__global__ void k_ln_gelu_res(const float* __restrict__ lnw, const float* __restrict__ lnb)
{
    int row = blockIdx.x; int tid = threadIdx.x;
    float a = g_attn[(size_t)row * DM + tid];
    float s = a, q = a * a;
    __shared__ float rs[4], rq[4];
    #pragma unroll
    for (int o = 16; o; o >>= 1) {
        s += __shfl_xor_sync(0xffffffffu, s, o);
        q += __shfl_xor_sync(0xffffffffu, q, o);
    }
    if ((tid & 31) == 0) { rs[tid >> 5] = s; rq[tid >> 5] = q; }
    __syncthreads();
    float ts = rs[0] + rs[1] + rs[2] + rs[3];
    float tq = rq[0] + rq[1] + rq[2] + rq[3];
    float mean = ts * (1.f / DM);
    float var  = tq * (1.f / DM) - mean * mean;
    float ln = (a - mean) * rsqrtf(var + 1e-5f) * lnw[tid] + lnb[tid];
    g_hb[(size_t)row * DM + tid] = geluf(ln) + g_h0[(size_t)row * DM + tid];
}

// ---------------- Mamba mid: conv+silu, x_proj, dt_proj+softplus, scan, gate ---
__global__ void __launch_bounds__(256, 1) k_mamba(
    const float* __restrict__ conv_w, const float* __restrict__ conv_b,
    const float* __restrict__ x_proj_w, const float* __restrict__ dt_proj_w,
    const float* __restrict__ dt_proj_b, const float* __restrict__ A_log,
    const float* __restrict__ D_ssm)
{
    extern __shared__ float sm[];
    float* xc_s  = sm;                      // PN*DIN
    float* dl_s  = xc_s + PN * DIN;         // PN*DIN
    float* xpw_s = dl_s + PN * DIN;         // 40*DIN transposed
    float* dbl_s = xpw_s + 40 * DIN;        // PN*40

    int bn = blockIdx.x, tid = threadIdx.x, d = tid;

    for (int i = tid; i < 40 * DIN; i += 256) {
        int j = i / DIN, dd = i % DIN;
        xpw_s[dd * 40 + j] = x_proj_w[i];
    }

    float cw0 = conv_w[d * 4], cw1 = conv_w[d * 4 + 1], cw2 = conv_w[d * 4 + 2], cw3 = conv_w[d * 4 + 3];
    float cb = conv_b[d];
    float w1 = 0.f, w2 = 0.f, w3 = 0.f;
    const float* xzb = g_xz + (size_t)bn * PN * 2 * DIN;
    for (int t = 0; t < PN; t++) {
        float xv = xzb[t * 2 * DIN + d];
        float c = w1 * cw0 + w2 * cw1 + w3 * cw2 + xv * cw3 + cb;
        w1 = w2; w2 = w3; w3 = xv;
        xc_s[t * DIN + d] = siluf(c);
    }
    __syncthreads();

    for (int idx = tid; idx < PN * 40; idx += 256) {
        int t = idx / 40, j = idx % 40;
        const float* xr = xc_s + t * DIN;
        float acc = 0.f;
        #pragma unroll 8
        for (int dd = 0; dd < DIN; dd++) acc += xr[dd] * xpw_s[dd * 40 + j];
        dbl_s[idx] = acc;
    }
    __syncthreads();

    float dtw[DTR];
    #pragma unroll
    for (int r = 0; r < DTR; r++) dtw[r] = dt_proj_w[d * DTR + r];
    float dtb = dt_proj_b[d];
    for (int t = 0; t < PN; t++) {
        float a = dtb;
        #pragma unroll
        for (int r = 0; r < DTR; r++) a += dbl_s[t * 40 + r] * dtw[r];
        dl_s[t * DIN + d] = (a > 20.f) ? a : log1pf(expf(a));
    }
    __syncthreads();

    float Ar[DS];
    #pragma unroll
    for (int s = 0; s < DS; s++) Ar[s] = -expf(A_log[d * DS + s]);
    float hst[DS];
    #pragma unroll
    for (int s = 0; s < DS; s++) hst[s] = 0.f;
    float Dd = D_ssm[d];
    float* yb = g_y + (size_t)bn * PN * DIN;
    for (int t = 0; t < PN; t++) {
        float dlt = dl_s[t * DIN + d];
        float u = xc_s[t * DIN + d];
        float du = dlt * u;
        float y = 0.f;
        const float* dr = dbl_s + t * 40;
        #pragma unroll
        for (int s = 0; s < DS; s++) {
            float dA = __expf(dlt * Ar[s]);
            hst[s] = dA * hst[s] + du * dr[8 + s];
            y += hst[s] * dr[24 + s];
        }
        y += Dd * u;
        float zv = xzb[t * 2 * DIN + DIN + d];
        y *= siluf(zv);
        yb[t * DIN + d] = y;
    }
}

// ---------------- mlp2 split-K reduce + bias + GELU ----------------
__global__ void k_mlp2_reduce(const float* __restrict__ mlp2_b)
{
    int idx = blockIdx.x * 256 + threadIdx.x;
    if (idx >= BN_TOT * 2 * PRED) return;
    float s = 0.f;
    #pragma unroll
    for (int z = 0; z < KSPLIT; z++) s += g_parts[(size_t)z * BN_TOT * 2 * PRED + idx];
    s += mlp2_b[idx % (2 * PRED)];
    g_gbuf[idx] = geluf(s);
}

// ---------------- mlp3 + de-normalize + transpose store ----------------
__global__ void k_final(const float* __restrict__ mlp3_w, const float* __restrict__ mlp3_b,
                        const float* __restrict__ revin_w, const float* __restrict__ revin_b,
                        float* __restrict__ out)
{
    int bn = blockIdx.x; int tid = threadIdx.x;
    __shared__ float gs[2 * PRED];
    for (int i = tid; i < 2 * PRED; i += PRED) gs[i] = g_gbuf[bn * 2 * PRED + i];
    __syncthreads();
    float acc = mlp3_b[tid];
    const float* wr = mlp3_w + tid * 2 * PRED;
    #pragma unroll 8
    for (int j = 0; j < 2 * PRED; j++) acc += gs[j] * wr[j];
    int b = bn / NVAR, v = bn % NVAR;
    float o = (acc - revin_b[v]) / (revin_w[v] + 1e-10f);
    o = o * g_std[bn] + g_mean[bn];
    out[(b * PRED + tid) * NVAR + v] = o;
}

// ---------------- launch ----------------
extern "C" void kernel_launch(void* const* d_in, const int* in_sizes, int n_in,
                              void* d_out, int out_size)
{
    const float* x         = (const float*)d_in[0];
    const float* revin_w   = (const float*)d_in[1];
    const float* revin_b   = (const float*)d_in[2];
    const float* mlp1_w    = (const float*)d_in[3];
    const float* mlp1_b    = (const float*)d_in[4];
    const float* mk_w      = (const float*)d_in[5];
    const float* mv_w      = (const float*)d_in[6];
    const float* ln_w      = (const float*)d_in[7];
    const float* ln_b      = (const float*)d_in[8];
    const float* in_proj_w = (const float*)d_in[9];
    const float* conv_w    = (const float*)d_in[10];
    const float* conv_b    = (const float*)d_in[11];
    const float* x_proj_w  = (const float*)d_in[12];
    const float* dt_proj_w = (const float*)d_in[13];
    const float* dt_proj_b = (const float*)d_in[14];
    const float* A_log     = (const float*)d_in[15];
    const float* D_ssm     = (const float*)d_in[16];
    const float* out_proj_w= (const float*)d_in[17];
    const float* mlp2_w    = (const float*)d_in[18];
    const float* mlp2_b    = (const float*)d_in[19];
    const float* mlp3_w    = (const float*)d_in[20];
    const float* mlp3_b    = (const float*)d_in[21];
    float* out = (float*)d_out;

    float *h0, *S, *attn, *hb, *xz, *y, *y2, *parts;
    cudaGetSymbolAddress((void**)&h0,    g_h0);
    cudaGetSymbolAddress((void**)&S,     g_S);
    cudaGetSymbolAddress((void**)&attn,  g_attn);
    cudaGetSymbolAddress((void**)&hb,    g_hb);
    cudaGetSymbolAddress((void**)&xz,    g_xz);
    cudaGetSymbolAddress((void**)&y,     g_y);
    cudaGetSymbolAddress((void**)&y2,    g_y2);
    cudaGetSymbolAddress((void**)&parts, g_parts);

    const int mamba_smem = (PN * DIN * 2 + 40 * DIN + PN * 40) * 4;
    cudaFuncSetAttribute(k_mamba, cudaFuncAttributeMaxDynamicSharedMemorySize, mamba_smem);

    // 1. RevIN + patches + mlp1
    k_revin_mlp1<<<BN_TOT, 128>>>(x, revin_w, revin_b, mlp1_w, mlp1_b);
    // 2. scores S = h @ mk_w^T        (21504 x 512 x 128)
    k_gemm128<<<dim3(ROWS / 128, SEA / 128), 256>>>(h0, mk_w, S, ROWS, SEA, DM);
    // 3. softmax
    k_softmax<<<ROWS, 128>>>(S);
    // 4. attn = P @ mv_w^T            (21504 x 128 x 512)
    k_gemm128<<<dim3(ROWS / 128, DM / 128), 256>>>(S, mv_w, attn, ROWS, DM, SEA);
    // 5. LN + GELU + residual -> hb
    k_ln_gelu_res<<<ROWS, 128>>>(ln_w, ln_b);
    // 6. xz = hb @ in_proj_w^T        (21504 x 512 x 128)
    k_gemm128<<<dim3(ROWS / 128, (2 * DIN) / 128), 256>>>(hb, in_proj_w, xz, ROWS, 2 * DIN, DM);
    // 7. mamba mid -> y
    k_mamba<<<BN_TOT, 256, mamba_smem>>>(conv_w, conv_b, x_proj_w, dt_proj_w, dt_proj_b, A_log, D_ssm);
    // 8. y2 = y @ out_proj_w^T        (21504 x 128 x 256)
    k_gemm128<<<dim3(ROWS / 128, DM / 128), 256>>>(y, out_proj_w, y2, ROWS, DM, DIN);
    // 9. mlp2 split-K partials: (336 x 8192) @ (192 x 8192)^T
    k_gemm_nt<<<dim3((BN_TOT + 63) / 64, (2 * PRED + 63) / 64, KSPLIT), 256>>>(
        y2, mlp2_w, parts, BN_TOT, 2 * PRED, PN * DM, (PN * DM) / KSPLIT);
    // 10. reduce + bias + GELU
    k_mlp2_reduce<<<(BN_TOT * 2 * PRED + 255) / 256, 256>>>(mlp2_b);
    // 11. mlp3 + de-norm + transposed store
    k_final<<<BN_TOT, PRED>>>(mlp3_w, mlp3_b, revin_w, revin_b, out);
}

// round 4
// speedup vs baseline: 1.3646x; 1.3389x over previous
#include <cuda_runtime.h>
#include <cstdint>

#define BB 16
#define TT 512
#define NVAR 21
#define PS 16
#define STR 8
#define PRED 96
#define DM 128
#define DS 16
#define DIN 256
#define DTR 8
#define SEA 512
#define PN 64
#define BN_TOT (BB*NVAR)      /* 336 */
#define ROWS (BN_TOT*PN)      /* 21504 */
#define KSPLIT 16

// ---------------- scratch (static device globals; no allocation) ----------------
__device__ float g_h0[ROWS*DM];
__device__ float g_S[ROWS*SEA];
__device__ float g_attn[ROWS*DM];
__device__ float g_hb[ROWS*DM];
__device__ float g_xz[ROWS*2*DIN];
__device__ float g_y[ROWS*DIN];
__device__ float g_y2[ROWS*DM];
__device__ float g_parts[KSPLIT*BN_TOT*2*PRED];
__device__ float g_gbuf[BN_TOT*2*PRED];
__device__ float g_mean[BN_TOT];
__device__ float g_std[BN_TOT];

__device__ __forceinline__ float geluf(float x) {
    return 0.5f * x * (1.0f + erff(x * 0.70710678118654752f));
}
__device__ __forceinline__ float siluf(float x) {
    return x / (1.0f + expf(-x));
}
__device__ __forceinline__ float tf32r(float x) {
    uint32_t u; asm("cvt.rna.tf32.f32 %0, %1;" : "=r"(u) : "f"(x));
    return __uint_as_float(u);
}

// ---------------- kernel 1: RevIN stats + patches + mlp1 ----------------
__global__ void k_revin_mlp1(const float* __restrict__ x,
                             const float* __restrict__ revin_w,
                             const float* __restrict__ revin_b,
                             const float* __restrict__ mlp1_w,
                             const float* __restrict__ mlp1_b)
{
    int bn = blockIdx.x;
    int b = bn / NVAR, v = bn % NVAR;
    int tid = threadIdx.x;
    __shared__ float xs[TT];
    __shared__ float rs[4], rq[4];

    float sum = 0.f, sq = 0.f;
    for (int t = tid; t < TT; t += 128) {
        float val = x[(b * TT + t) * NVAR + v];
        xs[t] = val;
        sum += val; sq += val * val;
    }
    #pragma unroll
    for (int o = 16; o; o >>= 1) {
        sum += __shfl_xor_sync(0xffffffffu, sum, o);
        sq  += __shfl_xor_sync(0xffffffffu, sq , o);
    }
    if ((tid & 31) == 0) { rs[tid >> 5] = sum; rq[tid >> 5] = sq; }
    __syncthreads();
    float ts = rs[0] + rs[1] + rs[2] + rs[3];
    float tq = rq[0] + rq[1] + rq[2] + rq[3];
    float mean = ts * (1.f / TT);
    float var  = tq * (1.f / TT) - mean * mean;
    float stdv = sqrtf(var + 1e-5f);
    float rstd = 1.f / stdv;
    if (tid == 0) { g_mean[bn] = mean; g_std[bn] = stdv; }

    float rw = revin_w[v], rb = revin_b[v];
    for (int t = tid; t < TT; t += 128)
        xs[t] = (xs[t] - mean) * rstd * rw + rb;
    __syncthreads();

    float w[PS];
    #pragma unroll
    for (int s = 0; s < PS; s++) w[s] = mlp1_w[tid * PS + s];
    float bias = mlp1_b[tid];
    for (int p = 0; p < PN; p++) {
        int base = p * STR;
        float acc = bias;
        #pragma unroll
        for (int s = 0; s < PS; s++) {
            int t = base + s; if (t > TT - 1) t = TT - 1;
            acc += xs[t] * w[s];
        }
        g_h0[(bn * PN + p) * DM + tid] = acc;
    }
}

// ---------------- tf32 tensor-core NT GEMM ----------------
// C[M,N] = A[M,K] @ B[N,K]^T, fp32 accumulate, tf32 inputs.
// BM in {64,128}; BN=128; K%32==0; M%BM==0; N%128==0.
// 8 warps: MW=BM/32 warps along M, NW=8/MW along N; warp tile 32 x (128/NW).
template<int BM>
__global__ void __launch_bounds__(256, 2) k_gemm_tf32(
    const float* __restrict__ A, const float* __restrict__ B, float* __restrict__ C,
    int M, int N, int K)
{
    constexpr int BN = 128;
    constexpr int MW = BM / 32;         // 2 or 4
    constexpr int NW = 8 / MW;          // 4 or 2
    constexpr int WN = BN / NW;         // 32 or 64
    constexpr int NI = WN / 8;          // 4 or 8
    constexpr int LDP = 36;             // padded row (floats): bank = (4*row + k) % 32

    __shared__ float As[BM][LDP];
    __shared__ float Bs[BN][LDP];

    int tid = threadIdx.x;
    int m0 = blockIdx.x * BM;
    int n0 = blockIdx.y * BN;
    int warp = tid >> 5, lane = tid & 31;
    int wm = (warp % MW) * 32;
    int wn = (warp / MW) * WN;
    int g = lane >> 2, tig = lane & 3;

    // global load mapping
    constexpr int ATPR = 256 / BM;           // threads per A row (2 or 4)
    constexpr int AF4  = 8 / ATPR;           // float4 per thread for A (4 or 2)
    int arow = tid / ATPR;
    int acol = (tid % ATPR) * (AF4 * 4);
    int brow = tid >> 1;
    int bcol = (tid & 1) * 16;
    const float* Ap = A + (size_t)(m0 + arow) * K + acol;
    const float* Bp = B + (size_t)(n0 + brow) * K + bcol;

    float acc[2][NI][4];
    #pragma unroll
    for (int mi = 0; mi < 2; mi++)
        #pragma unroll
        for (int ni = 0; ni < NI; ni++)
            #pragma unroll
            for (int r = 0; r < 4; r++) acc[mi][ni][r] = 0.f;

    for (int k0 = 0; k0 < K; k0 += 32) {
        float4 av[AF4], bv[4];
        #pragma unroll
        for (int i = 0; i < AF4; i++) av[i] = *(const float4*)(Ap + k0 + i * 4);
        #pragma unroll
        for (int i = 0; i < 4;   i++) bv[i] = *(const float4*)(Bp + k0 + i * 4);
        __syncthreads();
        #pragma unroll
        for (int i = 0; i < AF4; i++) {
            float* d = &As[arow][acol + i * 4];
            d[0] = tf32r(av[i].x); d[1] = tf32r(av[i].y);
            d[2] = tf32r(av[i].z); d[3] = tf32r(av[i].w);
        }
        #pragma unroll
        for (int i = 0; i < 4; i++) {
            float* d = &Bs[brow][bcol + i * 4];
            d[0] = tf32r(bv[i].x); d[1] = tf32r(bv[i].y);
            d[2] = tf32r(bv[i].z); d[3] = tf32r(bv[i].w);
        }
        __syncthreads();

        #pragma unroll
        for (int kk = 0; kk < 32; kk += 8) {
            uint32_t af[2][4];
            #pragma unroll
            for (int mi = 0; mi < 2; mi++) {
                int mb = wm + mi * 16;
                af[mi][0] = __float_as_uint(As[mb + g    ][kk + tig    ]);
                af[mi][1] = __float_as_uint(As[mb + g + 8][kk + tig    ]);
                af[mi][2] = __float_as_uint(As[mb + g    ][kk + tig + 4]);
                af[mi][3] = __float_as_uint(As[mb + g + 8][kk + tig + 4]);
            }
            #pragma unroll
            for (int ni = 0; ni < NI; ni++) {
                int nb = wn + ni * 8;
                uint32_t b0 = __float_as_uint(Bs[nb + g][kk + tig    ]);
                uint32_t b1 = __float_as_uint(Bs[nb + g][kk + tig + 4]);
                #pragma unroll
                for (int mi = 0; mi < 2; mi++) {
                    asm volatile(
                        "mma.sync.aligned.m16n8k8.row.col.f32.tf32.tf32.f32 "
                        "{%0,%1,%2,%3}, {%4,%5,%6,%7}, {%8,%9}, {%0,%1,%2,%3};"
                        : "+f"(acc[mi][ni][0]), "+f"(acc[mi][ni][1]),
                          "+f"(acc[mi][ni][2]), "+f"(acc[mi][ni][3])
                        : "r"(af[mi][0]), "r"(af[mi][1]), "r"(af[mi][2]), "r"(af[mi][3]),
                          "r"(b0), "r"(b1));
                }
            }
        }
    }

    #pragma unroll
    for (int mi = 0; mi < 2; mi++) {
        #pragma unroll
        for (int ni = 0; ni < NI; ni++) {
            float* cp = C + (size_t)(m0 + wm + mi * 16 + g) * N + n0 + wn + ni * 8 + 2 * tig;
            cp[0] = acc[mi][ni][0]; cp[1] = acc[mi][ni][1];
            cp += (size_t)8 * N;
            cp[0] = acc[mi][ni][2]; cp[1] = acc[mi][ni][3];
        }
    }
}

// ---------------- generic NT SGEMM (64x64) for mlp2 split-K ----------------
__global__ void __launch_bounds__(256) k_gemm_nt(
    const float* __restrict__ A, const float* __restrict__ B, float* __restrict__ C,
    int M, int N, int K, int klen)
{
    __shared__ float As[16][68];
    __shared__ float Bs[16][68];
    int m0 = blockIdx.x * 64;
    int n0 = blockIdx.y * 64;
    int kb = blockIdx.z * klen;
    C += (size_t)blockIdx.z * M * N;
    int tid = threadIdx.x;
    int tm = tid >> 4, tn = tid & 15;
    int lr = tid >> 2;
    int lk = (tid & 3) * 4;
    bool aValid = (m0 + lr) < M;
    const float* Ap = A + (size_t)(m0 + lr) * K + lk;
    const float* Bp = B + (size_t)(n0 + lr) * K + lk;

    float acc[4][4];
    #pragma unroll
    for (int i = 0; i < 4; i++)
        #pragma unroll
        for (int j = 0; j < 4; j++) acc[i][j] = 0.f;

    for (int k = kb; k < kb + klen; k += 16) {
        float4 av = aValid ? *(const float4*)(Ap + k) : make_float4(0.f, 0.f, 0.f, 0.f);
        float4 bv = *(const float4*)(Bp + k);
        __syncthreads();
        As[lk + 0][lr] = av.x; As[lk + 1][lr] = av.y; As[lk + 2][lr] = av.z; As[lk + 3][lr] = av.w;
        Bs[lk + 0][lr] = bv.x; Bs[lk + 1][lr] = bv.y; Bs[lk + 2][lr] = bv.z; Bs[lk + 3][lr] = bv.w;
        __syncthreads();
        #pragma unroll
        for (int kk = 0; kk < 16; kk++) {
            float4 a = *(const float4*)&As[kk][tm * 4];
            float4 b = *(const float4*)&Bs[kk][tn * 4];
            acc[0][0] += a.x * b.x; acc[0][1] += a.x * b.y; acc[0][2] += a.x * b.z; acc[0][3] += a.x * b.w;
            acc[1][0] += a.y * b.x; acc[1][1] += a.y * b.y; acc[1][2] += a.y * b.z; acc[1][3] += a.y * b.w;
            acc[2][0] += a.z * b.x; acc[2][1] += a.z * b.y; acc[2][2] += a.z * b.z; acc[2][3] += a.z * b.w;
            acc[3][0] += a.w * b.x; acc[3][1] += a.w * b.y; acc[3][2] += a.w * b.z; acc[3][3] += a.w * b.w;
        }
    }
    #pragma unroll
    for (int i = 0; i < 4; i++) {
        int row = m0 + tm * 4 + i;
        if (row < M) {
            float* cp = C + (size_t)row * N + n0 + tn * 4;
            cp[0] = acc[i][0]; cp[1] = acc[i][1]; cp[2] = acc[i][2]; cp[3] = acc[i][3];
        }
    }
}

// ---------------- softmax over rows of 512 (in place) ----------------
__global__ void k_softmax(float* __restrict__ S)
{
    int row = blockIdx.x; int tid = threadIdx.x;
    float* p = S + (size_t)row * SEA;
    float v0 = p[tid], v1 = p[tid + 128], v2 = p[tid + 256], v3 = p[tid + 384];
    float m = fmaxf(fmaxf(v0, v1), fmaxf(v2, v3));
    __shared__ float rr[4];
    __shared__ float ss[4];
    #pragma unroll
    for (int o = 16; o; o >>= 1) m = fmaxf(m, __shfl_xor_sync(0xffffffffu, m, o));
    if ((tid & 31) == 0) rr[tid >> 5] = m;
    __syncthreads();
    m = fmaxf(fmaxf(rr[0], rr[1]), fmaxf(rr[2], rr[3]));
    v0 = expf(v0 - m); v1 = expf(v1 - m); v2 = expf(v2 - m); v3 = expf(v3 - m);
    float s = v0 + v1 + v2 + v3;
    #pragma unroll
    for (int o = 16; o; o >>= 1) s += __shfl_xor_sync(0xffffffffu, s, o);
    if ((tid & 31) == 0) ss[tid >> 5] = s;
    __syncthreads();
    s = ss[0] + ss[1] + ss[2] + ss[3];
    float inv = 1.f / s;
    p[tid] = v0 * inv; p[tid + 128] = v1 * inv; p[tid + 256] = v2 * inv; p[tid + 384] = v3 * inv;
}

// ---------------- LayerNorm + exact GELU + residual ----------------
__global__ void k_ln_gelu_res(const float* __restrict__ lnw, const float* __restrict__ lnb)
{
    int row = blockIdx.x; int tid = threadIdx.x;
    float a = g_attn[(size_t)row * DM + tid];
    float s = a, q = a * a;
    __shared__ float rs[4], rq[4];
    #pragma unroll
    for (int o = 16; o; o >>= 1) {
        s += __shfl_xor_sync(0xffffffffu, s, o);
        q += __shfl_xor_sync(0xffffffffu, q, o);
    }
    if ((tid & 31) == 0) { rs[tid >> 5] = s; rq[tid >> 5] = q; }
    __syncthreads();
    float ts = rs[0] + rs[1] + rs[2] + rs[3];
    float tq = rq[0] + rq[1] + rq[2] + rq[3];
    float mean = ts * (1.f / DM);
    float var  = tq * (1.f / DM) - mean * mean;
    float ln = (a - mean) * rsqrtf(var + 1e-5f) * lnw[tid] + lnb[tid];
    g_hb[(size_t)row * DM + tid] = geluf(ln) + g_h0[(size_t)row * DM + tid];
}

// ---------------- Mamba mid: conv+silu, x_proj, dt_proj+softplus, scan, gate ---
__global__ void __launch_bounds__(256, 1) k_mamba(
    const float* __restrict__ conv_w, const float* __restrict__ conv_b,
    const float* __restrict__ x_proj_w, const float* __restrict__ dt_proj_w,
    const float* __restrict__ dt_proj_b, const float* __restrict__ A_log,
    const float* __restrict__ D_ssm)
{
    extern __shared__ float sm[];
    float* xc_s  = sm;                      // PN*DIN
    float* dl_s  = xc_s + PN * DIN;         // PN*DIN
    float* xpw_s = dl_s + PN * DIN;         // 40*DIN transposed
    float* dbl_s = xpw_s + 40 * DIN;        // PN*40

    int bn = blockIdx.x, tid = threadIdx.x, d = tid;

    for (int i = tid; i < 40 * DIN; i += 256) {
        int j = i / DIN, dd = i % DIN;
        xpw_s[dd * 40 + j] = x_proj_w[i];
    }

    float cw0 = conv_w[d * 4], cw1 = conv_w[d * 4 + 1], cw2 = conv_w[d * 4 + 2], cw3 = conv_w[d * 4 + 3];
    float cb = conv_b[d];
    float w1 = 0.f, w2 = 0.f, w3 = 0.f;
    const float* xzb = g_xz + (size_t)bn * PN * 2 * DIN;
    for (int t = 0; t < PN; t++) {
        float xv = xzb[t * 2 * DIN + d];
        float c = w1 * cw0 + w2 * cw1 + w3 * cw2 + xv * cw3 + cb;
        w1 = w2; w2 = w3; w3 = xv;
        xc_s[t * DIN + d] = siluf(c);
    }
    __syncthreads();

    for (int idx = tid; idx < PN * 40; idx += 256) {
        int t = idx / 40, j = idx % 40;
        const float* xr = xc_s + t * DIN;
        float acc = 0.f;
        #pragma unroll 8
        for (int dd = 0; dd < DIN; dd++) acc += xr[dd] * xpw_s[dd * 40 + j];
        dbl_s[idx] = acc;
    }
    __syncthreads();

    float dtw[DTR];
    #pragma unroll
    for (int r = 0; r < DTR; r++) dtw[r] = dt_proj_w[d * DTR + r];
    float dtb = dt_proj_b[d];
    for (int t = 0; t < PN; t++) {
        float a = dtb;
        #pragma unroll
        for (int r = 0; r < DTR; r++) a += dbl_s[t * 40 + r] * dtw[r];
        dl_s[t * DIN + d] = (a > 20.f) ? a : log1pf(expf(a));
    }
    __syncthreads();

    float Ar[DS];
    #pragma unroll
    for (int s = 0; s < DS; s++) Ar[s] = -expf(A_log[d * DS + s]);
    float hst[DS];
    #pragma unroll
    for (int s = 0; s < DS; s++) hst[s] = 0.f;
    float Dd = D_ssm[d];
    float* yb = g_y + (size_t)bn * PN * DIN;
    for (int t = 0; t < PN; t++) {
        float dlt = dl_s[t * DIN + d];
        float u = xc_s[t * DIN + d];
        float du = dlt * u;
        float y = 0.f;
        const float* dr = dbl_s + t * 40;
        #pragma unroll
        for (int s = 0; s < DS; s++) {
            float dA = __expf(dlt * Ar[s]);
            hst[s] = dA * hst[s] + du * dr[8 + s];
            y += hst[s] * dr[24 + s];
        }
        y += Dd * u;
        float zv = xzb[t * 2 * DIN + DIN + d];
        y *= siluf(zv);
        yb[t * DIN + d] = y;
    }
}

// ---------------- mlp2 split-K reduce + bias + GELU ----------------
__global__ void k_mlp2_reduce(const float* __restrict__ mlp2_b)
{
    int idx = blockIdx.x * 256 + threadIdx.x;
    if (idx >= BN_TOT * 2 * PRED) return;
    float s = 0.f;
    #pragma unroll
    for (int z = 0; z < KSPLIT; z++) s += g_parts[(size_t)z * BN_TOT * 2 * PRED + idx];
    s += mlp2_b[idx % (2 * PRED)];
    g_gbuf[idx] = geluf(s);
}

// ---------------- mlp3 + de-normalize + transpose store ----------------
__global__ void k_final(const float* __restrict__ mlp3_w, const float* __restrict__ mlp3_b,
                        const float* __restrict__ revin_w, const float* __restrict__ revin_b,
                        float* __restrict__ out)
{
    int bn = blockIdx.x; int tid = threadIdx.x;
    __shared__ float gs[2 * PRED];
    for (int i = tid; i < 2 * PRED; i += PRED) gs[i] = g_gbuf[bn * 2 * PRED + i];
    __syncthreads();
    float acc = mlp3_b[tid];
    const float* wr = mlp3_w + tid * 2 * PRED;
    #pragma unroll 8
    for (int j = 0; j < 2 * PRED; j++) acc += gs[j] * wr[j];
    int b = bn / NVAR, v = bn % NVAR;
    float o = (acc - revin_b[v]) / (revin_w[v] + 1e-10f);
    o = o * g_std[bn] + g_mean[bn];
    out[(b * PRED + tid) * NVAR + v] = o;
}

// ---------------- launch ----------------
extern "C" void kernel_launch(void* const* d_in, const int* in_sizes, int n_in,
                              void* d_out, int out_size)
{
    const float* x         = (const float*)d_in[0];
    const float* revin_w   = (const float*)d_in[1];
    const float* revin_b   = (const float*)d_in[2];
    const float* mlp1_w    = (const float*)d_in[3];
    const float* mlp1_b    = (const float*)d_in[4];
    const float* mk_w      = (const float*)d_in[5];
    const float* mv_w      = (const float*)d_in[6];
    const float* ln_w      = (const float*)d_in[7];
    const float* ln_b      = (const float*)d_in[8];
    const float* in_proj_w = (const float*)d_in[9];
    const float* conv_w    = (const float*)d_in[10];
    const float* conv_b    = (const float*)d_in[11];
    const float* x_proj_w  = (const float*)d_in[12];
    const float* dt_proj_w = (const float*)d_in[13];
    const float* dt_proj_b = (const float*)d_in[14];
    const float* A_log     = (const float*)d_in[15];
    const float* D_ssm     = (const float*)d_in[16];
    const float* out_proj_w= (const float*)d_in[17];
    const float* mlp2_w    = (const float*)d_in[18];
    const float* mlp2_b    = (const float*)d_in[19];
    const float* mlp3_w    = (const float*)d_in[20];
    const float* mlp3_b    = (const float*)d_in[21];
    float* out = (float*)d_out;

    float *h0, *S, *attn, *hb, *xz, *y, *y2, *parts;
    cudaGetSymbolAddress((void**)&h0,    g_h0);
    cudaGetSymbolAddress((void**)&S,     g_S);
    cudaGetSymbolAddress((void**)&attn,  g_attn);
    cudaGetSymbolAddress((void**)&hb,    g_hb);
    cudaGetSymbolAddress((void**)&xz,    g_xz);
    cudaGetSymbolAddress((void**)&y,     g_y);
    cudaGetSymbolAddress((void**)&y2,    g_y2);
    cudaGetSymbolAddress((void**)&parts, g_parts);

    const int mamba_smem = (PN * DIN * 2 + 40 * DIN + PN * 40) * 4;
    cudaFuncSetAttribute(k_mamba, cudaFuncAttributeMaxDynamicSharedMemorySize, mamba_smem);

    // 1. RevIN + patches + mlp1
    k_revin_mlp1<<<BN_TOT, 128>>>(x, revin_w, revin_b, mlp1_w, mlp1_b);
    // 2. scores S = h @ mk_w^T        (21504 x 512 x 128)  tf32 TC
    k_gemm_tf32<128><<<dim3(ROWS / 128, SEA / 128), 256>>>(h0, mk_w, S, ROWS, SEA, DM);
    // 3. softmax
    k_softmax<<<ROWS, 128>>>(S);
    // 4. attn = P @ mv_w^T            (21504 x 128 x 512)  tf32 TC, BM=64 for grid
    k_gemm_tf32<64><<<dim3(ROWS / 64, DM / 128), 256>>>(S, mv_w, attn, ROWS, DM, SEA);
    // 5. LN + GELU + residual -> hb
    k_ln_gelu_res<<<ROWS, 128>>>(ln_w, ln_b);
    // 6. xz = hb @ in_proj_w^T        (21504 x 512 x 128)  tf32 TC
    k_gemm_tf32<128><<<dim3(ROWS / 128, (2 * DIN) / 128), 256>>>(hb, in_proj_w, xz, ROWS, 2 * DIN, DM);
    // 7. mamba mid -> y
    k_mamba<<<BN_TOT, 256, mamba_smem>>>(conv_w, conv_b, x_proj_w, dt_proj_w, dt_proj_b, A_log, D_ssm);
    // 8. y2 = y @ out_proj_w^T        (21504 x 128 x 256)  tf32 TC, BM=64
    k_gemm_tf32<64><<<dim3(ROWS / 64, DM / 128), 256>>>(y, out_proj_w, y2, ROWS, DM, DIN);
    // 9. mlp2 split-K partials: (336 x 8192) @ (192 x 8192)^T
    k_gemm_nt<<<dim3((BN_TOT + 63) / 64, (2 * PRED + 63) / 64, KSPLIT), 256>>>(
        y2, mlp2_w, parts, BN_TOT, 2 * PRED, PN * DM, (PN * DM) / KSPLIT);
    // 10. reduce + bias + GELU
    k_mlp2_reduce<<<(BN_TOT * 2 * PRED + 255) / 256, 256>>>(mlp2_b);
    // 11. mlp3 + de-norm + transposed store
    k_final<<<BN_TOT, PRED>>>(mlp3_w, mlp3_b, revin_w, revin_b, out);
}